// round 13
// baseline (speedup 1.0000x reference)
#include <cuda_runtime.h>
#include <cstdint>

// ---------------- problem constants (fixed by this input set) ----------------
#define BATCH    8
#define NPTS     8192
#define NTOT     65536
#define NPOINT   512
#define NSAMPLE  32
#define CIN      64
#define R2       (0.1f * 0.1f)

// d_out packing (float32), tuple flattened in return order:
#define OFF_XYZ   0                                   // new_xyz  [8,512,3]
#define OFF_IDX   (BATCH * NPOINT * 3)                // new_idx  [8,512]
#define OFF_FEAT  (OFF_IDX + BATCH * NPOINT)          // new_feat [8,128,512]
#define OFF_SIDS  (OFF_FEAT + BATCH * 128 * NPOINT)   // sample_ids [8,512,32]

// ---------------- scratch (device globals; no runtime allocation) ------------
__device__ float        g_new_xyz[BATCH * NPOINT * 3];
__device__ float        g_featT[(size_t)NTOT * CIN];  // [n][c] transposed features
__device__ volatile int g_progress[BATCH];            // centers completed per batch
__device__ int          g_tr_done;                    // finished transpose blocks

// ---------------- packed f32x2 helpers (bit-exact per-lane fp32) -------------
__device__ __forceinline__ unsigned long long f2_add(unsigned long long a, unsigned long long b) {
    unsigned long long r;
    asm("add.rn.f32x2 %0, %1, %2;" : "=l"(r) : "l"(a), "l"(b));
    return r;
}
__device__ __forceinline__ unsigned long long f2_mul(unsigned long long a, unsigned long long b) {
    unsigned long long r;
    asm("mul.rn.f32x2 %0, %1, %2;" : "=l"(r) : "l"(a), "l"(b));
    return r;
}
__device__ __forceinline__ unsigned long long f2_pack(float lo, float hi) {
    unsigned long long r;
    asm("mov.b64 %0, {%1, %2};" : "=l"(r) : "f"(lo), "f"(hi));
    return r;
}
__device__ __forceinline__ void f2_unpack(unsigned long long v, float& lo, float& hi) {
    asm("mov.b64 {%0, %1}, %2;" : "=f"(lo), "=f"(hi) : "l"(v));
}
__device__ __forceinline__ unsigned redux_max_u32(unsigned v) {
    unsigned r;
    asm("redux.sync.max.u32 %0, %1, 0xffffffff;" : "=r"(r) : "r"(v));
    return r;
}

extern __shared__ float dyn_smem[];

// ---------------- MLP gemm helpers (256 active threads, 8x8 tiles) -----------
__device__ __forceinline__ void fma_tile(float acc[8][8],
                                         const float4& a0, const float4& a1,
                                         const float4& b0, const float4& b1) {
    const float a[8]  = {a0.x, a0.y, a0.z, a0.w, a1.x, a1.y, a1.z, a1.w};
    const float bb[8] = {b0.x, b0.y, b0.z, b0.w, b1.x, b1.y, b1.z, b1.w};
#pragma unroll
    for (int i = 0; i < 8; i++)
#pragma unroll
        for (int j = 0; j < 8; j++) acc[i][j] += a[i] * bb[j];
}

// acc[i][0..3] -> cols c0..c0+3 ; acc[i][4..7] -> cols c1..c1+3
template <int K, int LDA>
__device__ __forceinline__ void gemm8x8(const float* __restrict__ A,
                                        const float* __restrict__ Bm,
                                        int o0, int c0, int c1, float acc[8][8]) {
#pragma unroll
    for (int i = 0; i < 8; i++)
#pragma unroll
        for (int j = 0; j < 8; j++) acc[i][j] = 0.0f;

    float4 a0 = *(const float4*)&A[o0];
    float4 a1 = *(const float4*)&A[o0 + 4];
    float4 b0 = *(const float4*)&Bm[c0];
    float4 b1 = *(const float4*)&Bm[c1];
#pragma unroll 4
    for (int k = 0; k < K - 1; k++) {
        float4 na0 = *(const float4*)&A[(k + 1) * LDA + o0];
        float4 na1 = *(const float4*)&A[(k + 1) * LDA + o0 + 4];
        float4 nb0 = *(const float4*)&Bm[(k + 1) * 256 + c0];
        float4 nb1 = *(const float4*)&Bm[(k + 1) * 256 + c1];
        fma_tile(acc, a0, a1, b0, b1);
        a0 = na0; a1 = na1; b0 = nb0; b1 = nb1;
    }
    fma_tile(acc, a0, a1, b0, b1);
}

// =============================================================================
// Reset kernel: zero the cross-block handshake counters (graph replays reuse
// device globals, so this must run before the mega kernel each replay).
// =============================================================================
__global__ void reset_kernel() {
    if (threadIdx.x < BATCH) g_progress[threadIdx.x] = 0;
    if (threadIdx.x == 0) g_tr_done = 0;
}

// =============================================================================
// Mega kernel, 776 blocks x 512 threads:
//   blocks 0..7     : FPS (one batch each) + progress publication every 8 iters
//   blocks 8..263   : feature transpose + completion counter
//   blocks 264..775 : fused ballq + gather + MLP for one 8-center group,
//                     spin-waiting on FPS progress (pipelined under FPS).
// =============================================================================
__global__ void __launch_bounds__(512) mega_kernel(const float* __restrict__ xyz,
                                                   const float* __restrict__ feat,
                                                   const float* __restrict__ W0,
                                                   const float* __restrict__ b0v,
                                                   const float* __restrict__ W1,
                                                   const float* __restrict__ b1v,
                                                   const float* __restrict__ W2,
                                                   const float* __restrict__ b2v,
                                                   float* __restrict__ out) {
    const int t = threadIdx.x;
    const int bid = blockIdx.x;

    __shared__ unsigned long long red[2][16];
    __shared__ int sm_ids_sh[8][NSAMPLE];

    // ------------------------------------------------------------------ FPS
    if (bid < BATCH) {
        float4* spts = (float4*)dyn_smem;             // [8192] float4 = 128KB
        const int b = bid;
        const float* src = xyz + (size_t)b * NPTS * 3;

        float f[48];
        {
            const float4* s4 = (const float4*)src;
            float4* f4 = (float4*)f;
#pragma unroll
            for (int i = 0; i < 12; i++) f4[i] = s4[t * 12 + i];
        }
        unsigned long long pxp[8], pyp[8], pzp[8];
        float dd[16];
#pragma unroll
        for (int a = 0; a < 8; a++) {
            pxp[a] = f2_pack(f[6 * a + 0], f[6 * a + 3]);
            pyp[a] = f2_pack(f[6 * a + 1], f[6 * a + 4]);
            pzp[a] = f2_pack(f[6 * a + 2], f[6 * a + 5]);
        }
#pragma unroll
        for (int j = 0; j < 16; j++) {
            dd[j] = 1e10f;
            spts[t * 16 + j] = make_float4(f[3 * j + 0], f[3 * j + 1], f[3 * j + 2], 0.0f);
        }
        if (t == 0) {
            g_new_xyz[(size_t)(b * NPOINT) * 3 + 0] = f[0];
            g_new_xyz[(size_t)(b * NPOINT) * 3 + 1] = f[1];
            g_new_xyz[(size_t)(b * NPOINT) * 3 + 2] = f[2];
            out[OFF_IDX + b * NPOINT] = 0.0f;
            out[OFF_XYZ + (size_t)(b * NPOINT) * 3 + 0] = f[0];
            out[OFF_XYZ + (size_t)(b * NPOINT) * 3 + 1] = f[1];
            out[OFF_XYZ + (size_t)(b * NPOINT) * 3 + 2] = f[2];
        }
        __syncthreads();

        const float4 p0 = spts[0];
        unsigned long long nlx = f2_pack(-p0.x, -p0.x);
        unsigned long long nly = f2_pack(-p0.y, -p0.y);
        unsigned long long nlz = f2_pack(-p0.z, -p0.z);

        const int lane = t & 31;
        const int wid = t >> 5;
        const int base = t * 16;

        for (int it = 1; it < NPOINT; ++it) {
            float m = 0.0f;       // dd >= 0 -> u32 bit max == float max
            int mi = 0;
#pragma unroll
            for (int a = 0; a < 8; a++) {
                unsigned long long dx = f2_add(pxp[a], nlx);
                unsigned long long dy = f2_add(pyp[a], nly);
                unsigned long long dz = f2_add(pzp[a], nlz);
                unsigned long long s  = f2_add(f2_add(f2_mul(dx, dx), f2_mul(dy, dy)),
                                               f2_mul(dz, dz));
                float d2l, d2h;
                f2_unpack(s, d2l, d2h);
                const float n0 = fminf(dd[2 * a + 0], d2l);
                const float n1 = fminf(dd[2 * a + 1], d2h);
                dd[2 * a + 0] = n0;
                dd[2 * a + 1] = n1;
                if (n0 > m) { m = n0; mi = 2 * a + 0; }   // strict > : lowest idx on tie
                if (n1 > m) { m = n1; mi = 2 * a + 1; }
            }
            const unsigned mu = __float_as_uint(m);
            const unsigned wm = redux_max_u32(mu);
            const unsigned bal = __ballot_sync(0xffffffffu, mu == wm);
            const int srcl = __ffs(bal) - 1;
            const int gidx = __shfl_sync(0xffffffffu, base + mi, srcl);
            if (lane == 0)
                red[it & 1][wid] = ((unsigned long long)wm << 32) | (unsigned)gidx;
            __syncthreads();

            const unsigned long long pv = red[it & 1][lane & 15];
            const unsigned pval = (unsigned)(pv >> 32);
            const unsigned vm = redux_max_u32(pval);
            const unsigned bal2 = __ballot_sync(0xffffffffu, pval == vm);
            const int wsrc = __ffs(bal2) - 1;
            const int idx = __shfl_sync(0xffffffffu, (int)(unsigned)pv, wsrc);

            const float4 w = spts[idx];
            nlx = f2_pack(-w.x, -w.x);
            nly = f2_pack(-w.y, -w.y);
            nlz = f2_pack(-w.z, -w.z);
            if (t == 0) {
                g_new_xyz[(size_t)(b * NPOINT + it) * 3 + 0] = w.x;
                g_new_xyz[(size_t)(b * NPOINT + it) * 3 + 1] = w.y;
                g_new_xyz[(size_t)(b * NPOINT + it) * 3 + 2] = w.z;
                out[OFF_IDX + b * NPOINT + it] = (float)idx;
                out[OFF_XYZ + (size_t)(b * NPOINT + it) * 3 + 0] = w.x;
                out[OFF_XYZ + (size_t)(b * NPOINT + it) * 3 + 1] = w.y;
                out[OFF_XYZ + (size_t)(b * NPOINT + it) * 3 + 2] = w.z;
                if ((it & 7) == 7) {           // release-publish every 8 centers
                    __threadfence();
                    g_progress[b] = it + 1;
                }
            }
        }
        return;
    }

    // ------------------------------------------------------------ transpose
    if (bid < BATCH + 256) {
        float* tile = dyn_smem;                       // 32*33 floats
        const int bb = bid - BATCH;                   // 0..255
        const int tx = t & 31, ty = t >> 5;           // ty 0..15
        for (int ti = 0; ti < 16; ++ti) {
            const int tile_id = bb * 16 + ti;         // 0..4095
            const int n0 = (tile_id & 2047) * 32;
            const int c0 = (tile_id >> 11) * 32;
            __syncthreads();
            tile[ty * 33 + tx]        = feat[(size_t)(c0 + ty) * NTOT + (n0 + tx)];
            tile[(ty + 16) * 33 + tx] = feat[(size_t)(c0 + ty + 16) * NTOT + (n0 + tx)];
            __syncthreads();
            g_featT[(size_t)(n0 + ty) * CIN + (c0 + tx)]      = tile[tx * 33 + ty];
            g_featT[(size_t)(n0 + ty + 16) * CIN + (c0 + tx)] = tile[tx * 33 + ty + 16];
        }
        __threadfence();
        __syncthreads();
        if (t == 0) atomicAdd(&g_tr_done, 1);
        return;
    }

    // ------------------------------------------- fused ballq + gather + MLP
    {
        const int m_ = bid - (BATCH + 256);           // 0..511
        const int b = m_ & 7;
        const int cgrp = m_ >> 3;

        float* sW0 = dyn_smem;          // [67][64]  (k-major)
        float* sb0 = sW0 + 67 * 64;
        float* sW1 = sb0 + 64;          // [64][64]
        float* sb1 = sW1 + 64 * 64;
        float* sW2 = sb1 + 64;          // [64][128]
        float* sb2 = sW2 + 64 * 128;
        float* X0  = sb2 + 128;         // [67][256]  (reused as H2)
        float* H1  = X0 + 67 * 256;     // [64][256]
        // during ballq, the X0/H1 region holds staged xyz (3*8192 floats)
        float* spx = X0;
        float* spy = spx + NPTS;
        float* spz = spy + NPTS;

        // stage weights + xyz while FPS may still be running
        for (int i = t; i < 67 * 64; i += 512) { int k = i >> 6, o = i & 63;  sW0[i] = W0[o * 67 + k]; }
        for (int i = t; i < 64 * 64; i += 512) { int k = i >> 6, o = i & 63;  sW1[i] = W1[o * 64 + k]; }
        for (int i = t; i < 64 * 128; i += 512){ int k = i >> 7, o = i & 127; sW2[i] = W2[o * 64 + k]; }
        if (t < 64)  { sb0[t] = b0v[t]; sb1[t] = b1v[t]; }
        else if (t >= 128 && t < 256) { sb2[t - 128] = b2v[t - 128]; }
        {
            const float* src = xyz + (size_t)b * NPTS * 3;
            for (int i = t; i < NPTS; i += 512) {
                spx[i] = src[3 * i + 0];
                spy[i] = src[3 * i + 1];
                spz[i] = src[3 * i + 2];
            }
        }
        __syncthreads();

        // wait for our 8 centers + the transpose
        if (t == 0) {
            const int need = (cgrp + 1) * 8;
            while (g_progress[b] < need) __nanosleep(128);
            while (*(volatile int*)&g_tr_done < 256) __nanosleep(128);
            __threadfence();
        }
        __syncthreads();

        // ---- ball query: warps 0..7, one center each (exact semantics) ----
        const int w = t >> 5, lane = t & 31;
        if (w < 8) {
            const int gc = b * NPOINT + cgrp * 8 + w;
            const float cx = g_new_xyz[(size_t)gc * 3 + 0];
            const float cy = g_new_xyz[(size_t)gc * 3 + 1];
            const float cz = g_new_xyz[(size_t)gc * 3 + 2];

            int count = 0, first = -1;
            for (int chunk = 0; chunk < NPTS / 32; ++chunk) {
                const int p = chunk * 32 + lane;
                float dx = __fsub_rn(cx, spx[p]);
                float dy = __fsub_rn(cy, spy[p]);
                float dz = __fsub_rn(cz, spz[p]);
                float d2 = __fadd_rn(__fadd_rn(__fmul_rn(dx, dx), __fmul_rn(dy, dy)),
                                     __fmul_rn(dz, dz));
                const bool in = d2 < R2;
                const unsigned mm = __ballot_sync(0xffffffffu, in);
                if (mm) {
                    if (first < 0) first = chunk * 32 + __ffs(mm) - 1;
                    if (in) {
                        int rank = count + __popc(mm & ((1u << lane) - 1u));
                        if (rank < NSAMPLE) sm_ids_sh[w][rank] = p;
                    }
                    count += __popc(mm);
                    if (count >= NSAMPLE) break;
                }
            }
            __syncwarp();
            if (first < 0) first = 0;
            const int id = (lane < count) ? sm_ids_sh[w][lane] : first;
            sm_ids_sh[w][lane] = id;
            out[OFF_SIDS + (size_t)gc * NSAMPLE + lane] = (float)id;
        }
        __syncthreads();

        // ---- gather: thread pair (s, s+256) fills one sample column --------
        {
            const int s = t & 255;
            const int half = t >> 8;
            const int cl = s >> 5;
            const int gc = b * NPOINT + cgrp * 8 + cl;
            const int pid = sm_ids_sh[cl][s & 31];
            if (half == 0) {
                const float* p = xyz + ((size_t)b * NPTS + pid) * 3;
                X0[0 * 256 + s] = p[0] - g_new_xyz[(size_t)gc * 3 + 0];
                X0[1 * 256 + s] = p[1] - g_new_xyz[(size_t)gc * 3 + 1];
                X0[2 * 256 + s] = p[2] - g_new_xyz[(size_t)gc * 3 + 2];
            }
            const float4* fp = (const float4*)(g_featT + ((size_t)b * NPTS + pid) * CIN + half * 32);
#pragma unroll
            for (int q = 0; q < 8; q++) {
                float4 v = fp[q];
                const int r = 3 + half * 32 + 4 * q;
                X0[(r + 0) * 256 + s] = v.x;
                X0[(r + 1) * 256 + s] = v.y;
                X0[(r + 2) * 256 + s] = v.z;
                X0[(r + 3) * 256 + s] = v.w;
            }
        }
        __syncthreads();

        // ---- MLP on warps 0..7 (8x8 tiles); warps 8..15 park on barriers ---
        const int ot = t >> 5, st = t & 31;
        const int o0 = ot * 8;
        const int c0 = st * 4, c1 = 128 + st * 4;
        float acc[8][8];

        if (t < 256) {
            gemm8x8<67, 64>(sW0, X0, o0, c0, c1, acc);
#pragma unroll
            for (int i = 0; i < 8; i++) {
                const float bi = sb0[o0 + i];
                float4 r0 = make_float4(fmaxf(acc[i][0] + bi, 0.0f), fmaxf(acc[i][1] + bi, 0.0f),
                                        fmaxf(acc[i][2] + bi, 0.0f), fmaxf(acc[i][3] + bi, 0.0f));
                float4 r1 = make_float4(fmaxf(acc[i][4] + bi, 0.0f), fmaxf(acc[i][5] + bi, 0.0f),
                                        fmaxf(acc[i][6] + bi, 0.0f), fmaxf(acc[i][7] + bi, 0.0f));
                *(float4*)&H1[(o0 + i) * 256 + c0] = r0;
                *(float4*)&H1[(o0 + i) * 256 + c1] = r1;
            }
        }
        __syncthreads();

        if (t < 256) {
            gemm8x8<64, 64>(sW1, H1, o0, c0, c1, acc);
#pragma unroll
            for (int i = 0; i < 8; i++) {
                const float bi = sb1[o0 + i];
                float4 r0 = make_float4(fmaxf(acc[i][0] + bi, 0.0f), fmaxf(acc[i][1] + bi, 0.0f),
                                        fmaxf(acc[i][2] + bi, 0.0f), fmaxf(acc[i][3] + bi, 0.0f));
                float4 r1 = make_float4(fmaxf(acc[i][4] + bi, 0.0f), fmaxf(acc[i][5] + bi, 0.0f),
                                        fmaxf(acc[i][6] + bi, 0.0f), fmaxf(acc[i][7] + bi, 0.0f));
                *(float4*)&X0[(o0 + i) * 256 + c0] = r0;
                *(float4*)&X0[(o0 + i) * 256 + c1] = r1;
            }
        }
        __syncthreads();

        if (t < 256) {
            const int g = st >> 3;
#pragma unroll
            for (int half = 0; half < 2; ++half) {
                gemm8x8<64, 128>(sW2 + half * 64, X0, o0, c0, c1, acc);
#pragma unroll
                for (int i = 0; i < 8; i++) {
                    const float bi = sb2[half * 64 + o0 + i];
                    float m0 = 0.0f, m1 = 0.0f;   // ReLU outputs are >= 0
#pragma unroll
                    for (int j = 0; j < 4; j++) {
                        m0 = fmaxf(m0, fmaxf(acc[i][j] + bi, 0.0f));
                        m1 = fmaxf(m1, fmaxf(acc[i][4 + j] + bi, 0.0f));
                    }
                    m0 = fmaxf(m0, __shfl_xor_sync(0xffffffffu, m0, 1));
                    m1 = fmaxf(m1, __shfl_xor_sync(0xffffffffu, m1, 1));
                    m0 = fmaxf(m0, __shfl_xor_sync(0xffffffffu, m0, 2));
                    m1 = fmaxf(m1, __shfl_xor_sync(0xffffffffu, m1, 2));
                    m0 = fmaxf(m0, __shfl_xor_sync(0xffffffffu, m0, 4));
                    m1 = fmaxf(m1, __shfl_xor_sync(0xffffffffu, m1, 4));
                    if ((st & 7) == 0) {
                        const int o = half * 64 + o0 + i;
                        out[OFF_FEAT + ((size_t)b * 128 + o) * NPOINT + cgrp * 8 + g]     = m0;
                        out[OFF_FEAT + ((size_t)b * 128 + o) * NPOINT + cgrp * 8 + 4 + g] = m1;
                    }
                }
            }
        }
    }
}

// =============================================================================
extern "C" void kernel_launch(void* const* d_in, const int* in_sizes, int n_in,
                              void* d_out, int out_size) {
    const float* xyz  = (const float*)d_in[0];
    const float* feat = (const float*)d_in[1];
    const float* W0   = (const float*)d_in[3];
    const float* b0   = (const float*)d_in[4];
    const float* W1   = (const float*)d_in[5];
    const float* b1   = (const float*)d_in[6];
    const float* W2   = (const float*)d_in[7];
    const float* b2   = (const float*)d_in[8];
    float* out = (float*)d_out;

    const int smem_mega = (67*64 + 64 + 64*64 + 64 + 64*128 + 128
                           + 67*256 + 64*256) * sizeof(float);     // 201472

    cudaFuncSetAttribute(mega_kernel, cudaFuncAttributeMaxDynamicSharedMemorySize, smem_mega);

    reset_kernel<<<1, 32>>>();
    mega_kernel<<<BATCH + 256 + BATCH * (NPOINT / 8), 512, smem_mega>>>(
        xyz, feat, W0, b0, W1, b1, W2, b2, out);
}

// round 15
// speedup vs baseline: 1.0044x; 1.0044x over previous
#include <cuda_runtime.h>
#include <cstdint>

// ---------------- problem constants (fixed by this input set) ----------------
#define BATCH    8
#define NPTS     8192
#define NTOT     65536
#define NPOINT   512
#define NSAMPLE  32
#define CIN      64
#define R2       (0.1f * 0.1f)

// d_out packing (float32), tuple flattened in return order:
#define OFF_XYZ   0                                   // new_xyz  [8,512,3]
#define OFF_IDX   (BATCH * NPOINT * 3)                // new_idx  [8,512]
#define OFF_FEAT  (OFF_IDX + BATCH * NPOINT)          // new_feat [8,128,512]
#define OFF_SIDS  (OFF_FEAT + BATCH * 128 * NPOINT)   // sample_ids [8,512,32]

// ---------------- scratch (device globals; no runtime allocation) ------------
__device__ float        g_new_xyz[BATCH * NPOINT * 3];
__device__ float        g_featT[(size_t)NTOT * CIN];  // [n][c] transposed features
__device__ volatile int g_progress[BATCH];            // centers completed per batch
__device__ int          g_tr_done;                    // finished transpose blocks

// ---------------- packed f32x2 helpers (bit-exact per-lane fp32) -------------
__device__ __forceinline__ unsigned long long f2_add(unsigned long long a, unsigned long long b) {
    unsigned long long r;
    asm("add.rn.f32x2 %0, %1, %2;" : "=l"(r) : "l"(a), "l"(b));
    return r;
}
__device__ __forceinline__ unsigned long long f2_mul(unsigned long long a, unsigned long long b) {
    unsigned long long r;
    asm("mul.rn.f32x2 %0, %1, %2;" : "=l"(r) : "l"(a), "l"(b));
    return r;
}
__device__ __forceinline__ unsigned long long f2_pack(float lo, float hi) {
    unsigned long long r;
    asm("mov.b64 %0, {%1, %2};" : "=l"(r) : "f"(lo), "f"(hi));
    return r;
}
__device__ __forceinline__ void f2_unpack(unsigned long long v, float& lo, float& hi) {
    asm("mov.b64 {%0, %1}, %2;" : "=f"(lo), "=f"(hi) : "l"(v));
}
__device__ __forceinline__ unsigned redux_max_u32(unsigned v) {
    unsigned r;
    asm("redux.sync.max.u32 %0, %1, 0xffffffff;" : "=r"(r) : "r"(v));
    return r;
}

extern __shared__ float dyn_smem[];

// ---------------- MLP gemm helpers (256 active threads, 8x8 tiles) -----------
__device__ __forceinline__ void fma_tile(float acc[8][8],
                                         const float4& a0, const float4& a1,
                                         const float4& b0, const float4& b1) {
    const float a[8]  = {a0.x, a0.y, a0.z, a0.w, a1.x, a1.y, a1.z, a1.w};
    const float bb[8] = {b0.x, b0.y, b0.z, b0.w, b1.x, b1.y, b1.z, b1.w};
#pragma unroll
    for (int i = 0; i < 8; i++)
#pragma unroll
        for (int j = 0; j < 8; j++) acc[i][j] += a[i] * bb[j];
}

// acc[i][0..3] -> cols c0..c0+3 ; acc[i][4..7] -> cols c1..c1+3
template <int K, int LDA>
__device__ __forceinline__ void gemm8x8(const float* __restrict__ A,
                                        const float* __restrict__ Bm,
                                        int o0, int c0, int c1, float acc[8][8]) {
#pragma unroll
    for (int i = 0; i < 8; i++)
#pragma unroll
        for (int j = 0; j < 8; j++) acc[i][j] = 0.0f;

    float4 a0 = *(const float4*)&A[o0];
    float4 a1 = *(const float4*)&A[o0 + 4];
    float4 b0 = *(const float4*)&Bm[c0];
    float4 b1 = *(const float4*)&Bm[c1];
#pragma unroll 4
    for (int k = 0; k < K - 1; k++) {
        float4 na0 = *(const float4*)&A[(k + 1) * LDA + o0];
        float4 na1 = *(const float4*)&A[(k + 1) * LDA + o0 + 4];
        float4 nb0 = *(const float4*)&Bm[(k + 1) * 256 + c0];
        float4 nb1 = *(const float4*)&Bm[(k + 1) * 256 + c1];
        fma_tile(acc, a0, a1, b0, b1);
        a0 = na0; a1 = na1; b0 = nb0; b1 = nb1;
    }
    fma_tile(acc, a0, a1, b0, b1);
}

// =============================================================================
// Reset kernel: zero the cross-block handshake counters (graph replays reuse
// device globals, so this must run before the mega kernel each replay).
// =============================================================================
__global__ void reset_kernel() {
    if (threadIdx.x < BATCH) g_progress[threadIdx.x] = 0;
    if (threadIdx.x == 0) g_tr_done = 0;
}

// =============================================================================
// Mega kernel, 776 blocks x 512 threads:
//   blocks 0..7     : FPS (one batch each) + progress publication every 8 iters
//   blocks 8..263   : feature transpose + completion counter
//   blocks 264..775 : fused ballq + gather + MLP for one 8-center group,
//                     spin-waiting on FPS progress (pipelined under FPS).
// =============================================================================
__global__ void __launch_bounds__(512) mega_kernel(const float* __restrict__ xyz,
                                                   const float* __restrict__ feat,
                                                   const float* __restrict__ W0,
                                                   const float* __restrict__ b0v,
                                                   const float* __restrict__ W1,
                                                   const float* __restrict__ b1v,
                                                   const float* __restrict__ W2,
                                                   const float* __restrict__ b2v,
                                                   float* __restrict__ out) {
    const int t = threadIdx.x;
    const int bid = blockIdx.x;

    __shared__ unsigned long long red[2][16];
    __shared__ int sm_ids_sh[8][NSAMPLE];

    // ------------------------------------------------------------------ FPS
    if (bid < BATCH) {
        float4* spts = (float4*)dyn_smem;             // [8192] float4 = 128KB
        const int b = bid;
        const float* src = xyz + (size_t)b * NPTS * 3;

        float f[48];
        {
            const float4* s4 = (const float4*)src;
            float4* f4 = (float4*)f;
#pragma unroll
            for (int i = 0; i < 12; i++) f4[i] = s4[t * 12 + i];
        }
        unsigned long long pxp[8], pyp[8], pzp[8];
        float dd[16];
#pragma unroll
        for (int a = 0; a < 8; a++) {
            pxp[a] = f2_pack(f[6 * a + 0], f[6 * a + 3]);
            pyp[a] = f2_pack(f[6 * a + 1], f[6 * a + 4]);
            pzp[a] = f2_pack(f[6 * a + 2], f[6 * a + 5]);
        }
#pragma unroll
        for (int j = 0; j < 16; j++) {
            dd[j] = 1e10f;
            spts[t * 16 + j] = make_float4(f[3 * j + 0], f[3 * j + 1], f[3 * j + 2], 0.0f);
        }
        if (t == 0) {
            g_new_xyz[(size_t)(b * NPOINT) * 3 + 0] = f[0];
            g_new_xyz[(size_t)(b * NPOINT) * 3 + 1] = f[1];
            g_new_xyz[(size_t)(b * NPOINT) * 3 + 2] = f[2];
            out[OFF_IDX + b * NPOINT] = 0.0f;
            out[OFF_XYZ + (size_t)(b * NPOINT) * 3 + 0] = f[0];
            out[OFF_XYZ + (size_t)(b * NPOINT) * 3 + 1] = f[1];
            out[OFF_XYZ + (size_t)(b * NPOINT) * 3 + 2] = f[2];
        }
        __syncthreads();

        const float4 p0 = spts[0];
        unsigned long long nlx = f2_pack(-p0.x, -p0.x);
        unsigned long long nly = f2_pack(-p0.y, -p0.y);
        unsigned long long nlz = f2_pack(-p0.z, -p0.z);

        const int lane = t & 31;
        const int wid = t >> 5;
        const int base = t * 16;

        for (int it = 1; it < NPOINT; ++it) {
            float m = 0.0f;       // dd >= 0 -> u32 bit max == float max
            int mi = 0;
#pragma unroll
            for (int a = 0; a < 8; a++) {
                unsigned long long dx = f2_add(pxp[a], nlx);
                unsigned long long dy = f2_add(pyp[a], nly);
                unsigned long long dz = f2_add(pzp[a], nlz);
                unsigned long long s  = f2_add(f2_add(f2_mul(dx, dx), f2_mul(dy, dy)),
                                               f2_mul(dz, dz));
                float d2l, d2h;
                f2_unpack(s, d2l, d2h);
                const float n0 = fminf(dd[2 * a + 0], d2l);
                const float n1 = fminf(dd[2 * a + 1], d2h);
                dd[2 * a + 0] = n0;
                dd[2 * a + 1] = n1;
                if (n0 > m) { m = n0; mi = 2 * a + 0; }   // strict > : lowest idx on tie
                if (n1 > m) { m = n1; mi = 2 * a + 1; }
            }
            const unsigned mu = __float_as_uint(m);
            const unsigned wm = redux_max_u32(mu);
            const unsigned bal = __ballot_sync(0xffffffffu, mu == wm);
            const int srcl = __ffs(bal) - 1;
            const int gidx = __shfl_sync(0xffffffffu, base + mi, srcl);
            if (lane == 0)
                red[it & 1][wid] = ((unsigned long long)wm << 32) | (unsigned)gidx;
            __syncthreads();

            const unsigned long long pv = red[it & 1][lane & 15];
            const unsigned pval = (unsigned)(pv >> 32);
            const unsigned vm = redux_max_u32(pval);
            const unsigned bal2 = __ballot_sync(0xffffffffu, pval == vm);
            const int wsrc = __ffs(bal2) - 1;
            const int idx = __shfl_sync(0xffffffffu, (int)(unsigned)pv, wsrc);

            const float4 w = spts[idx];
            nlx = f2_pack(-w.x, -w.x);
            nly = f2_pack(-w.y, -w.y);
            nlz = f2_pack(-w.z, -w.z);
            if (t == 0) {
                g_new_xyz[(size_t)(b * NPOINT + it) * 3 + 0] = w.x;
                g_new_xyz[(size_t)(b * NPOINT + it) * 3 + 1] = w.y;
                g_new_xyz[(size_t)(b * NPOINT + it) * 3 + 2] = w.z;
                out[OFF_IDX + b * NPOINT + it] = (float)idx;
                out[OFF_XYZ + (size_t)(b * NPOINT + it) * 3 + 0] = w.x;
                out[OFF_XYZ + (size_t)(b * NPOINT + it) * 3 + 1] = w.y;
                out[OFF_XYZ + (size_t)(b * NPOINT + it) * 3 + 2] = w.z;
                if ((it & 7) == 7) {           // release-publish every 8 centers
                    __threadfence();
                    g_progress[b] = it + 1;
                }
            }
        }
        return;
    }

    // ------------------------------------------------------------ transpose
    if (bid < BATCH + 256) {
        float* tile = dyn_smem;                       // 32*33 floats
        const int bb = bid - BATCH;                   // 0..255
        const int tx = t & 31, ty = t >> 5;           // ty 0..15
        for (int ti = 0; ti < 16; ++ti) {
            const int tile_id = bb * 16 + ti;         // 0..4095
            const int n0 = (tile_id & 2047) * 32;
            const int c0 = (tile_id >> 11) * 32;
            __syncthreads();
            tile[ty * 33 + tx]        = feat[(size_t)(c0 + ty) * NTOT + (n0 + tx)];
            tile[(ty + 16) * 33 + tx] = feat[(size_t)(c0 + ty + 16) * NTOT + (n0 + tx)];
            __syncthreads();
            g_featT[(size_t)(n0 + ty) * CIN + (c0 + tx)]      = tile[tx * 33 + ty];
            g_featT[(size_t)(n0 + ty + 16) * CIN + (c0 + tx)] = tile[tx * 33 + ty + 16];
        }
        __threadfence();
        __syncthreads();
        if (t == 0) atomicAdd(&g_tr_done, 1);
        return;
    }

    // ------------------------------------------- fused ballq + gather + MLP
    {
        const int m_ = bid - (BATCH + 256);           // 0..511
        const int b = m_ & 7;
        const int cgrp = m_ >> 3;

        float* sW0 = dyn_smem;          // [67][64]  (k-major)
        float* sb0 = sW0 + 67 * 64;
        float* sW1 = sb0 + 64;          // [64][64]
        float* sb1 = sW1 + 64 * 64;
        float* sW2 = sb1 + 64;          // [64][128]
        float* sb2 = sW2 + 64 * 128;
        float* X0  = sb2 + 128;         // [67][256]  (reused as H2)
        float* H1  = X0 + 67 * 256;     // [64][256]
        // during ballq, the X0/H1 region holds staged xyz (3*8192 floats)
        float* spx = X0;
        float* spy = spx + NPTS;
        float* spz = spy + NPTS;

        // stage weights + xyz while FPS may still be running
        for (int i = t; i < 67 * 64; i += 512) { int k = i >> 6, o = i & 63;  sW0[i] = W0[o * 67 + k]; }
        for (int i = t; i < 64 * 64; i += 512) { int k = i >> 6, o = i & 63;  sW1[i] = W1[o * 64 + k]; }
        for (int i = t; i < 64 * 128; i += 512){ int k = i >> 7, o = i & 127; sW2[i] = W2[o * 64 + k]; }
        if (t < 64)  { sb0[t] = b0v[t]; sb1[t] = b1v[t]; }
        else if (t >= 128 && t < 256) { sb2[t - 128] = b2v[t - 128]; }
        {
            const float* src = xyz + (size_t)b * NPTS * 3;
            for (int i = t; i < NPTS; i += 512) {
                spx[i] = src[3 * i + 0];
                spy[i] = src[3 * i + 1];
                spz[i] = src[3 * i + 2];
            }
        }
        __syncthreads();

        // wait for our 8 centers + the transpose
        if (t == 0) {
            const int need = (cgrp + 1) * 8;
            while (g_progress[b] < need) __nanosleep(128);
            while (*(volatile int*)&g_tr_done < 256) __nanosleep(128);
            __threadfence();
        }
        __syncthreads();

        // ---- ball query: warps 0..7, one center each (exact semantics) ----
        const int w = t >> 5, lane = t & 31;
        if (w < 8) {
            const int gc = b * NPOINT + cgrp * 8 + w;
            const float cx = g_new_xyz[(size_t)gc * 3 + 0];
            const float cy = g_new_xyz[(size_t)gc * 3 + 1];
            const float cz = g_new_xyz[(size_t)gc * 3 + 2];

            int count = 0, first = -1;
            for (int chunk = 0; chunk < NPTS / 32; ++chunk) {
                const int p = chunk * 32 + lane;
                float dx = __fsub_rn(cx, spx[p]);
                float dy = __fsub_rn(cy, spy[p]);
                float dz = __fsub_rn(cz, spz[p]);
                float d2 = __fadd_rn(__fadd_rn(__fmul_rn(dx, dx), __fmul_rn(dy, dy)),
                                     __fmul_rn(dz, dz));
                const bool in = d2 < R2;
                const unsigned mm = __ballot_sync(0xffffffffu, in);
                if (mm) {
                    if (first < 0) first = chunk * 32 + __ffs(mm) - 1;
                    if (in) {
                        int rank = count + __popc(mm & ((1u << lane) - 1u));
                        if (rank < NSAMPLE) sm_ids_sh[w][rank] = p;
                    }
                    count += __popc(mm);
                    if (count >= NSAMPLE) break;
                }
            }
            __syncwarp();
            if (first < 0) first = 0;
            const int id = (lane < count) ? sm_ids_sh[w][lane] : first;
            sm_ids_sh[w][lane] = id;
            out[OFF_SIDS + (size_t)gc * NSAMPLE + lane] = (float)id;
        }
        __syncthreads();

        // ---- gather: thread pair (s, s+256) fills one sample column --------
        {
            const int s = t & 255;
            const int half = t >> 8;
            const int cl = s >> 5;
            const int gc = b * NPOINT + cgrp * 8 + cl;
            const int pid = sm_ids_sh[cl][s & 31];
            if (half == 0) {
                const float* p = xyz + ((size_t)b * NPTS + pid) * 3;
                X0[0 * 256 + s] = p[0] - g_new_xyz[(size_t)gc * 3 + 0];
                X0[1 * 256 + s] = p[1] - g_new_xyz[(size_t)gc * 3 + 1];
                X0[2 * 256 + s] = p[2] - g_new_xyz[(size_t)gc * 3 + 2];
            }
            const float4* fp = (const float4*)(g_featT + ((size_t)b * NPTS + pid) * CIN + half * 32);
#pragma unroll
            for (int q = 0; q < 8; q++) {
                float4 v = fp[q];
                const int r = 3 + half * 32 + 4 * q;
                X0[(r + 0) * 256 + s] = v.x;
                X0[(r + 1) * 256 + s] = v.y;
                X0[(r + 2) * 256 + s] = v.z;
                X0[(r + 3) * 256 + s] = v.w;
            }
        }
        __syncthreads();

        // ---- MLP on warps 0..7 (8x8 tiles); warps 8..15 park on barriers ---
        const int ot = t >> 5, st = t & 31;
        const int o0 = ot * 8;
        const int c0 = st * 4, c1 = 128 + st * 4;
        float acc[8][8];

        if (t < 256) {
            gemm8x8<67, 64>(sW0, X0, o0, c0, c1, acc);
#pragma unroll
            for (int i = 0; i < 8; i++) {
                const float bi = sb0[o0 + i];
                float4 r0 = make_float4(fmaxf(acc[i][0] + bi, 0.0f), fmaxf(acc[i][1] + bi, 0.0f),
                                        fmaxf(acc[i][2] + bi, 0.0f), fmaxf(acc[i][3] + bi, 0.0f));
                float4 r1 = make_float4(fmaxf(acc[i][4] + bi, 0.0f), fmaxf(acc[i][5] + bi, 0.0f),
                                        fmaxf(acc[i][6] + bi, 0.0f), fmaxf(acc[i][7] + bi, 0.0f));
                *(float4*)&H1[(o0 + i) * 256 + c0] = r0;
                *(float4*)&H1[(o0 + i) * 256 + c1] = r1;
            }
        }
        __syncthreads();

        if (t < 256) {
            gemm8x8<64, 64>(sW1, H1, o0, c0, c1, acc);
#pragma unroll
            for (int i = 0; i < 8; i++) {
                const float bi = sb1[o0 + i];
                float4 r0 = make_float4(fmaxf(acc[i][0] + bi, 0.0f), fmaxf(acc[i][1] + bi, 0.0f),
                                        fmaxf(acc[i][2] + bi, 0.0f), fmaxf(acc[i][3] + bi, 0.0f));
                float4 r1 = make_float4(fmaxf(acc[i][4] + bi, 0.0f), fmaxf(acc[i][5] + bi, 0.0f),
                                        fmaxf(acc[i][6] + bi, 0.0f), fmaxf(acc[i][7] + bi, 0.0f));
                *(float4*)&X0[(o0 + i) * 256 + c0] = r0;
                *(float4*)&X0[(o0 + i) * 256 + c1] = r1;
            }
        }
        __syncthreads();

        if (t < 256) {
            const int g = st >> 3;
#pragma unroll
            for (int half = 0; half < 2; ++half) {
                gemm8x8<64, 128>(sW2 + half * 64, X0, o0, c0, c1, acc);
#pragma unroll
                for (int i = 0; i < 8; i++) {
                    const float bi = sb2[half * 64 + o0 + i];
                    float m0 = 0.0f, m1 = 0.0f;   // ReLU outputs are >= 0
#pragma unroll
                    for (int j = 0; j < 4; j++) {
                        m0 = fmaxf(m0, fmaxf(acc[i][j] + bi, 0.0f));
                        m1 = fmaxf(m1, fmaxf(acc[i][4 + j] + bi, 0.0f));
                    }
                    m0 = fmaxf(m0, __shfl_xor_sync(0xffffffffu, m0, 1));
                    m1 = fmaxf(m1, __shfl_xor_sync(0xffffffffu, m1, 1));
                    m0 = fmaxf(m0, __shfl_xor_sync(0xffffffffu, m0, 2));
                    m1 = fmaxf(m1, __shfl_xor_sync(0xffffffffu, m1, 2));
                    m0 = fmaxf(m0, __shfl_xor_sync(0xffffffffu, m0, 4));
                    m1 = fmaxf(m1, __shfl_xor_sync(0xffffffffu, m1, 4));
                    if ((st & 7) == 0) {
                        const int o = half * 64 + o0 + i;
                        out[OFF_FEAT + ((size_t)b * 128 + o) * NPOINT + cgrp * 8 + g]     = m0;
                        out[OFF_FEAT + ((size_t)b * 128 + o) * NPOINT + cgrp * 8 + 4 + g] = m1;
                    }
                }
            }
        }
    }
}

// =============================================================================
extern "C" void kernel_launch(void* const* d_in, const int* in_sizes, int n_in,
                              void* d_out, int out_size) {
    const float* xyz  = (const float*)d_in[0];
    const float* feat = (const float*)d_in[1];
    const float* W0   = (const float*)d_in[3];
    const float* b0   = (const float*)d_in[4];
    const float* W1   = (const float*)d_in[5];
    const float* b1   = (const float*)d_in[6];
    const float* W2   = (const float*)d_in[7];
    const float* b2   = (const float*)d_in[8];
    float* out = (float*)d_out;

    const int smem_mega = (67*64 + 64 + 64*64 + 64 + 64*128 + 128
                           + 67*256 + 64*256) * sizeof(float);     // 201472

    cudaFuncSetAttribute(mega_kernel, cudaFuncAttributeMaxDynamicSharedMemorySize, smem_mega);

    reset_kernel<<<1, 32>>>();
    mega_kernel<<<BATCH + 256 + BATCH * (NPOINT / 8), 512, smem_mega>>>(
        xyz, feat, W0, b0, W1, b1, W2, b2, out);
}